// round 9
// baseline (speedup 1.0000x reference)
#include <cuda_runtime.h>
#include <cuda_bf16.h>
#include <cstdint>

#define TPB  512
#define GRID 148

// ---- dynamic shared memory layout (bytes) ----
// h1 tiles: 128 rows x 128 bf16, padded row stride 272 B (conflict-free ldmatrix)
#define H1_STRIDE 272
#define H1A_OFF   0
#define H1B_OFF   34816                    // 128*272
#define PA_OFF    69632                    // 16 slots x 128 rows x f32    (8192)
#define PB_OFF    77824                    // 16 slots x 128 rows x float4 (32768)
#define W1_OFF    110592                   // packed layer-1 weights       (1536)
#define SMEM_TOTAL 112128

static __device__ __forceinline__ uint32_t smem_u32(const void* p) {
    uint32_t a;
    asm("{ .reg .u64 t; cvta.to.shared.u64 t, %1; cvt.u32.u64 %0, t; }" : "=r"(a) : "l"(p));
    return a;
}

static __device__ __forceinline__ uint32_t pack_bf16(float a, float b) {
    __nv_bfloat162 t = __floats2bfloat162_rn(a, b);
    return *reinterpret_cast<uint32_t*>(&t);
}

static __device__ __forceinline__ void ldsm_x4(uint32_t a[4], uint32_t addr) {
    asm volatile("ldmatrix.sync.aligned.m8n8.x4.shared.b16 {%0,%1,%2,%3}, [%4];"
                 : "=r"(a[0]), "=r"(a[1]), "=r"(a[2]), "=r"(a[3]) : "r"(addr));
}

static __device__ __forceinline__ void mma16816(float c[4], const uint32_t a[4],
                                                uint32_t b0, uint32_t b1) {
    asm volatile(
        "mma.sync.aligned.m16n8k16.row.col.f32.bf16.bf16.f32 "
        "{%0,%1,%2,%3}, {%4,%5,%6,%7}, {%8,%9}, {%0,%1,%2,%3};"
        : "+f"(c[0]), "+f"(c[1]), "+f"(c[2]), "+f"(c[3])
        : "r"(a[0]), "r"(a[1]), "r"(a[2]), "r"(a[3]), "r"(b0), "r"(b1));
}

__global__ void __launch_bounds__(TPB, 1) KroneNet_59485297049802_kernel(
    const float* __restrict__ x,
    const float* __restrict__ w1a, const float* __restrict__ w1b,
    const float* __restrict__ b1a, const float* __restrict__ b1b,
    const float* __restrict__ w2a, const float* __restrict__ w2b,
    const float* __restrict__ b2a, const float* __restrict__ b2b,
    const float* __restrict__ w3a, const float* __restrict__ w3b,
    const float* __restrict__ b3a, const float* __restrict__ b3b,
    float* __restrict__ out, int Bn)
{
    extern __shared__ __align__(16) char sm[];
    const uint32_t smb = smem_u32(sm);
    const int tid  = threadIdx.x;
    const int wid  = tid >> 5;
    const int lane = tid & 31;
    const int quad = lane >> 2;    // 0..7
    const int qlid = lane & 3;     // 0..3

    // stream split: s = wid&1 (0 = stream a, 1 = stream b); ngroup = wid>>1
    const int s  = wid & 1;
    const int ng = wid >> 1;       // 0..7, n-cols [16ng, 16ng+16)

    float*    pA  = reinterpret_cast<float*>(sm + PA_OFF);
    float4*   pB  = reinterpret_cast<float4*>(sm + PB_OFF);
    uint32_t* w1w = reinterpret_cast<uint32_t*>(sm + W1_OFF);

    // ---- one-time: pack layer-1 weights into SMEM (bf16x2, lane-major) ----
    // word index: ((s*2+g)*3 + which)*32 + lane ; which: 0=w.x pair, 1=w.y pair, 2=bias pair
    if (tid < 128) {
        const int s_ = tid >> 6, g_ = (tid >> 5) & 1, l_ = tid & 31;
        const int k0 = g_ * 64 + 2 * l_;
        const float* w1s_ = s_ ? w1b : w1a;
        const float* b1s_ = s_ ? b1b : b1a;
        const int W = ((s_ * 2 + g_) * 3) * 32 + l_;
        w1w[W]      = pack_bf16(w1s_[2 * k0],     w1s_[2 * k0 + 2]);
        w1w[W + 32] = pack_bf16(w1s_[2 * k0 + 1], w1s_[2 * k0 + 3]);
        w1w[W + 64] = pack_bf16(b1s_[k0],         b1s_[k0 + 1]);
    }

    const float* w2s = s ? w2b : w2a;

    // ---- persistent B fragments (this stream only): n = 16ng + 8j + quad ----
    uint32_t Bf[2][8][2];
    #pragma unroll
    for (int j = 0; j < 2; ++j) {
        const int n = 16 * ng + 8 * j + quad;
        #pragma unroll
        for (int kk = 0; kk < 8; ++kk) {
            const int k0 = 16 * kk + 2 * qlid;
            float2 lo = *reinterpret_cast<const float2*>(w2s + n * 128 + k0);
            float2 hi = *reinterpret_cast<const float2*>(w2s + n * 128 + k0 + 8);
            Bf[j][kk][0] = pack_bf16(lo.x, lo.y);
            Bf[j][kk][1] = pack_bf16(hi.x, hi.y);
        }
    }

    // ---- epilogue constants: D cols n = 16ng + 8j + 2qlid + h ----
    float biasC[2][2];
    float w3C[3][2][2];   // s==0 uses only [0]
    #pragma unroll
    for (int j = 0; j < 2; ++j)
        #pragma unroll
        for (int h = 0; h < 2; ++h) {
            const int n = 16 * ng + 8 * j + 2 * qlid + h;
            if (s == 0) {
                biasC[j][h]  = b2a[n];
                w3C[0][j][h] = w3a[n];
                w3C[1][j][h] = 0.f;
                w3C[2][j][h] = 0.f;
            } else {
                biasC[j][h]  = b2b[n];
                w3C[0][j][h] = w3b[n];
                w3C[1][j][h] = w3b[128 + n];
                w3C[2][j][h] = w3b[256 + n];
            }
        }
    const float s_b3a = b3a[0];
    const float s_b3b0 = b3b[0], s_b3b1 = b3b[1], s_b3b2 = b3b[2];

    // ldmatrix per-lane source address (m8n8.x4 over 16 rows x 16 cols bf16)
    const uint32_t lrow  = (uint32_t)((lane & 7) + ((lane >> 3) & 1) * 8);
    const uint32_t lcolb = (uint32_t)(((lane >> 4) & 1) * 16);
    const uint32_t aS = smb + (s ? H1B_OFF : H1A_OFF) + lrow * H1_STRIDE + lcolb;

    const int ntiles = Bn >> 7;
    const float2* x2 = reinterpret_cast<const float2*>(x);
    const __nv_bfloat162 z2 = __floats2bfloat162_rn(0.f, 0.f);

    __syncthreads();   // w1w visible to all

    for (int t = blockIdx.x; t < ntiles; t += gridDim.x) {
        // ---- layer 1: h1 = relu(W1 x + b1) -> bf16 SMEM (warp w: rows 8w..8w+7) ----
        {
            __nv_bfloat162 pw[2][2][3];   // [stream][g][which]
            #pragma unroll
            for (int ss = 0; ss < 2; ++ss)
                #pragma unroll
                for (int g = 0; g < 2; ++g)
                    #pragma unroll
                    for (int whch = 0; whch < 3; ++whch) {
                        uint32_t wv = w1w[((ss * 2 + g) * 3 + whch) * 32 + lane];
                        pw[ss][g][whch] = *reinterpret_cast<__nv_bfloat162*>(&wv);
                    }
            #pragma unroll
            for (int r = 0; r < 8; ++r) {
                const int row = wid * 8 + r;
                const int rg  = t * 128 + row;
                const float2 xa = x2[rg];
                const float2 xb = x2[Bn + rg];
                const __nv_bfloat162 xax = __bfloat162bfloat162(__float2bfloat16(xa.x));
                const __nv_bfloat162 xay = __bfloat162bfloat162(__float2bfloat16(xa.y));
                const __nv_bfloat162 xbx = __bfloat162bfloat162(__float2bfloat16(xb.x));
                const __nv_bfloat162 xby = __bfloat162bfloat162(__float2bfloat16(xb.y));
                char* rowa = sm + H1A_OFF + row * H1_STRIDE;
                char* rowb = sm + H1B_OFF + row * H1_STRIDE;
                #pragma unroll
                for (int g = 0; g < 2; ++g) {
                    __nv_bfloat162 ha = __hmax2(
                        __hfma2(xax, pw[0][g][0], __hfma2(xay, pw[0][g][1], pw[0][g][2])), z2);
                    __nv_bfloat162 hb = __hmax2(
                        __hfma2(xbx, pw[1][g][0], __hfma2(xby, pw[1][g][1], pw[1][g][2])), z2);
                    *reinterpret_cast<uint32_t*>(rowa + 128 * g + 4 * lane) =
                        *reinterpret_cast<uint32_t*>(&ha);
                    *reinterpret_cast<uint32_t*>(rowb + 128 * g + 4 * lane) =
                        *reinterpret_cast<uint32_t*>(&hb);
                }
            }
        }
        __syncthreads();

        // ---- layer 2 (HMMA, own stream), 2 m-tiles interleaved -> 4 chains ----
        #pragma unroll
        for (int ii = 0; ii < 4; ++ii) {
            const int i0 = 2 * ii, i1 = 2 * ii + 1;
            const uint32_t base0 = aS + (uint32_t)(i0 * 16 * H1_STRIDE);
            const uint32_t base1 = aS + (uint32_t)(i1 * 16 * H1_STRIDE);

            float c00[4] = {0.f, 0.f, 0.f, 0.f};
            float c01[4] = {0.f, 0.f, 0.f, 0.f};
            float c10[4] = {0.f, 0.f, 0.f, 0.f};
            float c11[4] = {0.f, 0.f, 0.f, 0.f};
            #pragma unroll
            for (int kk = 0; kk < 8; ++kk) {
                uint32_t af0[4], af1[4];
                ldsm_x4(af0, base0 + 32u * kk);
                ldsm_x4(af1, base1 + 32u * kk);
                mma16816(c00, af0, Bf[0][kk][0], Bf[0][kk][1]);
                mma16816(c01, af0, Bf[1][kk][0], Bf[1][kk][1]);
                mma16816(c10, af1, Bf[0][kk][0], Bf[0][kk][1]);
                mma16816(c11, af1, Bf[1][kk][0], Bf[1][kk][1]);
            }

            // ---- epilogue for the two m-tiles ----
            #pragma unroll
            for (int m = 0; m < 2; ++m) {
                const float* c0 = m ? c10 : c00;
                const float* c1 = m ? c11 : c01;
                const int i = m ? i1 : i0;

                const float v00 = fmaxf(c0[0] + biasC[0][0], 0.f);
                const float v01 = fmaxf(c0[1] + biasC[0][1], 0.f);
                const float v10 = fmaxf(c1[0] + biasC[1][0], 0.f);
                const float v11 = fmaxf(c1[1] + biasC[1][1], 0.f);
                const float u00 = fmaxf(c0[2] + biasC[0][0], 0.f);
                const float u01 = fmaxf(c0[3] + biasC[0][1], 0.f);
                const float u10 = fmaxf(c1[2] + biasC[1][0], 0.f);
                const float u11 = fmaxf(c1[3] + biasC[1][1], 0.f);

                // slot for 1-level reduction: lanes {0,1} and {2,3} pair up;
                // qlid 0 and 2 both store -> 16 slots per stream
                const int slot = ng * 2 + (qlid >> 1);

                if (s == 0) {
                    float p0 = v00 * w3C[0][0][0] + v01 * w3C[0][0][1]
                             + v10 * w3C[0][1][0] + v11 * w3C[0][1][1];
                    float p1 = u00 * w3C[0][0][0] + u01 * w3C[0][0][1]
                             + u10 * w3C[0][1][0] + u11 * w3C[0][1][1];
                    p0 += __shfl_xor_sync(0xFFFFFFFFu, p0, 1);
                    p1 += __shfl_xor_sync(0xFFFFFFFFu, p1, 1);
                    if ((qlid & 1) == 0) {
                        pA[slot * 128 + 16 * i + quad]     = p0;
                        pA[slot * 128 + 16 * i + quad + 8] = p1;
                    }
                } else {
                    float q0[3], q1[3];
                    #pragma unroll
                    for (int c = 0; c < 3; ++c) {
                        float s0 = v00 * w3C[c][0][0] + v01 * w3C[c][0][1]
                                 + v10 * w3C[c][1][0] + v11 * w3C[c][1][1];
                        float s1 = u00 * w3C[c][0][0] + u01 * w3C[c][0][1]
                                 + u10 * w3C[c][1][0] + u11 * w3C[c][1][1];
                        s0 += __shfl_xor_sync(0xFFFFFFFFu, s0, 1);
                        s1 += __shfl_xor_sync(0xFFFFFFFFu, s1, 1);
                        q0[c] = s0; q1[c] = s1;
                    }
                    if ((qlid & 1) == 0) {
                        pB[slot * 128 + 16 * i + quad]     = make_float4(q0[0], q0[1], q0[2], 0.f);
                        pB[slot * 128 + 16 * i + quad + 8] = make_float4(q1[0], q1[1], q1[2], 0.f);
                    }
                }
            }
        }
        __syncthreads();

        // ---- final: combine 16 slots per stream, softmax, store ----
        if (tid < 128) {
            const int row = tid;
            float oa = s_b3a;
            float o0 = s_b3b0, o1 = s_b3b1, o2 = s_b3b2;
            #pragma unroll
            for (int g = 0; g < 16; ++g) {
                oa += pA[g * 128 + row];
                const float4 qb = pB[g * 128 + row];
                o0 += qb.x; o1 += qb.y; o2 += qb.z;
            }
            const float t0 = oa * o0, t1 = oa * o1, t2 = oa * o2;
            const float mx = fmaxf(t0, fmaxf(t1, t2));
            const float e0 = expf(t0 - mx), e1 = expf(t1 - mx), e2 = expf(t2 - mx);
            const float inv = 1.f / (e0 + e1 + e2);
            const int rg = t * 128 + row;
            out[rg * 3 + 0] = e0 * inv;
            out[rg * 3 + 1] = e1 * inv;
            out[rg * 3 + 2] = e2 * inv;
        }
        // next-tile pA/pB writes are separated from these reads by the
        // h1 __syncthreads at the top of the next iteration.
    }
}

extern "C" void kernel_launch(void* const* d_in, const int* in_sizes, int n_in,
                              void* d_out, int out_size) {
    const float* x   = (const float*)d_in[0];
    const float* w1a = (const float*)d_in[1];
    const float* w1b = (const float*)d_in[2];
    const float* b1a = (const float*)d_in[3];
    const float* b1b = (const float*)d_in[4];
    const float* w2a = (const float*)d_in[5];
    const float* w2b = (const float*)d_in[6];
    const float* b2a = (const float*)d_in[7];
    const float* b2b = (const float*)d_in[8];
    const float* w3a = (const float*)d_in[9];
    const float* w3b = (const float*)d_in[10];
    const float* b3a = (const float*)d_in[11];
    const float* b3b = (const float*)d_in[12];
    float* out = (float*)d_out;

    int Bn = in_sizes[0] / 4;   // x is (2, B, 2) fp32

    cudaFuncSetAttribute(KroneNet_59485297049802_kernel,
                         cudaFuncAttributeMaxDynamicSharedMemorySize, SMEM_TOTAL);
    KroneNet_59485297049802_kernel<<<GRID, TPB, SMEM_TOTAL>>>(
        x, w1a, w1b, b1a, b1b, w2a, w2b, b2a, b2b, w3a, w3b, b3a, b3b, out, Bn);
}